// round 1
// baseline (speedup 1.0000x reference)
#include <cuda_runtime.h>

#define BATCH 16
#define CDIM 256
#define HW 4096
#define TK 16

// Scratch (no allocations allowed in kernel_launch)
__device__ float g_ynorm[BATCH * CDIM];               // 16 KB
__device__ float g_dist[BATCH * CDIM * CDIM];         // 4 MB
__device__ int   g_idx[BATCH * CDIM];                 // 16 KB

// ---------------------------------------------------------------------------
// 1) ynorm[b][j] = sum_k Y[b,j,k]^2     (one block per row)
// ---------------------------------------------------------------------------
__global__ void __launch_bounds__(256) ynorm_kernel(const float* __restrict__ Y) {
    int row = blockIdx.x;  // b*CDIM + j
    const float4* yp = (const float4*)(Y + (size_t)row * HW);
    int t = threadIdx.x;
    float s = 0.f;
#pragma unroll
    for (int it = 0; it < 4; ++it) {
        float4 v = yp[t + it * 256];
        s += v.x * v.x + v.y * v.y + v.z * v.z + v.w * v.w;
    }
#pragma unroll
    for (int o = 16; o; o >>= 1) s += __shfl_down_sync(0xffffffffu, s, o);
    __shared__ float ws[8];
    if ((t & 31) == 0) ws[t >> 5] = s;
    __syncthreads();
    if (t < 8) {
        float v = ws[t];
#pragma unroll
        for (int o = 4; o; o >>= 1) v += __shfl_down_sync(0xffu, v, o);
        if (t == 0) g_ynorm[row] = v;
    }
}

// ---------------------------------------------------------------------------
// 2) dist2[b][i][j] = ynorm[b][j] - 2 * dot(X[b,i,:], Y[b,j,:])
//    64x64 output tile per block, 256 threads, 4x4 micro-tile/thread, TK=16.
// ---------------------------------------------------------------------------
__global__ void __launch_bounds__(256) gemm_dist_kernel(const float* __restrict__ X,
                                                        const float* __restrict__ Y) {
    __shared__ float As[TK][68];   // [k][row], pad to 68 (272B rows, 16B aligned)
    __shared__ float Bs[TK][68];   // [k][col]

    const int b  = blockIdx.z;
    const int i0 = blockIdx.y * 64;
    const int j0 = blockIdx.x * 64;
    const float* A = X + (size_t)b * CDIM * HW;
    const float* B = Y + (size_t)b * CDIM * HW;

    const int t  = threadIdx.x;
    const int tx = t & 15;         // micro-tile col group
    const int ty = t >> 4;         // micro-tile row group
    const int lr = t >> 2;         // load row (0..63)
    const int lq = t & 3;          // load k-quad (0..3)

    float acc[4][4] = {};

    const float* aptr = A + (size_t)(i0 + lr) * HW + lq * 4;
    const float* bptr = B + (size_t)(j0 + lr) * HW + lq * 4;

    for (int kc = 0; kc < HW; kc += TK) {
        float4 av = *(const float4*)(aptr + kc);
        float4 bv = *(const float4*)(bptr + kc);
        __syncthreads();  // previous iter's compute done before overwrite
        As[lq * 4 + 0][lr] = av.x; As[lq * 4 + 1][lr] = av.y;
        As[lq * 4 + 2][lr] = av.z; As[lq * 4 + 3][lr] = av.w;
        Bs[lq * 4 + 0][lr] = bv.x; Bs[lq * 4 + 1][lr] = bv.y;
        Bs[lq * 4 + 2][lr] = bv.z; Bs[lq * 4 + 3][lr] = bv.w;
        __syncthreads();
#pragma unroll
        for (int k = 0; k < TK; ++k) {
            float4 a = *(const float4*)&As[k][ty * 4];
            float4 q = *(const float4*)&Bs[k][tx * 4];
            acc[0][0] += a.x * q.x; acc[0][1] += a.x * q.y; acc[0][2] += a.x * q.z; acc[0][3] += a.x * q.w;
            acc[1][0] += a.y * q.x; acc[1][1] += a.y * q.y; acc[1][2] += a.y * q.z; acc[1][3] += a.y * q.w;
            acc[2][0] += a.z * q.x; acc[2][1] += a.z * q.y; acc[2][2] += a.z * q.z; acc[2][3] += a.z * q.w;
            acc[3][0] += a.w * q.x; acc[3][1] += a.w * q.y; acc[3][2] += a.w * q.z; acc[3][3] += a.w * q.w;
        }
    }

    // Epilogue: d = ynorm[j] - 2*dot
    float yn[4];
#pragma unroll
    for (int jj = 0; jj < 4; ++jj) yn[jj] = g_ynorm[b * CDIM + j0 + tx * 4 + jj];
#pragma unroll
    for (int ii = 0; ii < 4; ++ii) {
        int i = i0 + ty * 4 + ii;
        float4 dv;
        dv.x = yn[0] - 2.f * acc[ii][0];
        dv.y = yn[1] - 2.f * acc[ii][1];
        dv.z = yn[2] - 2.f * acc[ii][2];
        dv.w = yn[3] - 2.f * acc[ii][3];
        *(float4*)&g_dist[((size_t)(b * CDIM) + i) * CDIM + j0 + tx * 4] = dv;
    }
}

// ---------------------------------------------------------------------------
// 3) argmin per row (tie -> lower index, matching jnp.argmin). One warp/row.
// ---------------------------------------------------------------------------
__global__ void __launch_bounds__(256) argmin_kernel() {
    int gwarp = (blockIdx.x * blockDim.x + threadIdx.x) >> 5;
    int lane  = threadIdx.x & 31;
    if (gwarp >= BATCH * CDIM) return;
    const float* row = g_dist + (size_t)gwarp * CDIM;
    float bv = 3.4e38f;
    int   bi = 0x7fffffff;
#pragma unroll
    for (int s = 0; s < CDIM; s += 32) {
        float v = row[s + lane];
        int idx = s + lane;
        if (v < bv || (v == bv && idx < bi)) { bv = v; bi = idx; }
    }
#pragma unroll
    for (int o = 16; o; o >>= 1) {
        float ov = __shfl_down_sync(0xffffffffu, bv, o);
        int   oi = __shfl_down_sync(0xffffffffu, bi, o);
        if (ov < bv || (ov == bv && oi < bi)) { bv = ov; bi = oi; }
    }
    if (lane == 0) g_idx[gwarp] = bi;
}

// ---------------------------------------------------------------------------
// 4) gather: out[b,i,:] = Y[b, idx[b,i], :]
// ---------------------------------------------------------------------------
__global__ void __launch_bounds__(256) gather_kernel(const float* __restrict__ Y,
                                                     float* __restrict__ out) {
    int row  = blockIdx.x >> 2;   // b*CDIM + i
    int part = blockIdx.x & 3;
    int b    = row >> 8;
    int src  = g_idx[row];
    const float4* yp = (const float4*)(Y + ((size_t)(b * CDIM + src)) * HW);
    float4*       op = (float4*)(out + (size_t)row * HW);
    int e = part * 1024 / 4 + threadIdx.x;   // part*256 + tid  (1024 float4 per row)
    op[e] = yp[e];
}

// ---------------------------------------------------------------------------
extern "C" void kernel_launch(void* const* d_in, const int* in_sizes, int n_in,
                              void* d_out, int out_size) {
    const float* x = (const float*)d_in[0];
    const float* y = (const float*)d_in[1];
    float* out = (float*)d_out;

    ynorm_kernel<<<BATCH * CDIM, 256>>>(y);

    dim3 g(CDIM / 64, CDIM / 64, BATCH);   // 4 x 4 x 16 = 256 blocks
    gemm_dist_kernel<<<g, 256>>>(x, y);

    argmin_kernel<<<(BATCH * CDIM * 32) / 256, 256>>>();   // 512 blocks

    gather_kernel<<<BATCH * CDIM * 4, 256>>>(y, out);
}

// round 2
// speedup vs baseline: 1.2350x; 1.2350x over previous
#include <cuda_runtime.h>

#define BATCH 16
#define CDIM 256
#define HW 4096
#define TK 16
#define NK (HW / TK)

// best (encoded_dist << 32 | j) per row; re-initialized every launch
__device__ unsigned long long g_best[BATCH * CDIM];

// ---------------- f32x2 helpers (sm_103a packed fp32) ----------------
__device__ __forceinline__ unsigned long long pack2(float x, float y) {
    unsigned long long r;
    asm("mov.b64 %0, {%1, %2};" : "=l"(r) : "f"(x), "f"(y));
    return r;
}
__device__ __forceinline__ unsigned long long dup2(float x) {
    unsigned long long r;
    asm("mov.b64 %0, {%1, %1};" : "=l"(r) : "f"(x));
    return r;
}
__device__ __forceinline__ unsigned long long fma2(unsigned long long a,
                                                   unsigned long long b,
                                                   unsigned long long c) {
    unsigned long long d;
    asm("fma.rn.f32x2 %0, %1, %2, %3;" : "=l"(d) : "l"(a), "l"(b), "l"(c));
    return d;
}
__device__ __forceinline__ float2 unpack2(unsigned long long v) {
    float2 f;
    asm("mov.b64 {%0, %1}, %2;" : "=f"(f.x), "=f"(f.y) : "l"(v));
    return f;
}

// ---------------------------------------------------------------------------
// 0) reset g_best (must happen every call: graph replays, atomics below)
// ---------------------------------------------------------------------------
__global__ void __launch_bounds__(256) init_kernel() {
    g_best[blockIdx.x * 256 + threadIdx.x] = 0xFFFFFFFFFFFFFFFFull;
}

// ---------------------------------------------------------------------------
// 1) Fused: dist2[i][j] = |y_j|^2 - 2*dot(x_i, y_j)  (+ per-row argmin via
//    packed atomicMin). 64x64 tile / CTA, 4x4 micro-tile, f32x2 FMAs,
//    double-buffered smem (1 barrier per k-chunk). ynorm computed in-flight
//    from this CTA's own B loads.
// ---------------------------------------------------------------------------
__global__ void __launch_bounds__(256, 2) gemm_argmin_kernel(const float* __restrict__ X,
                                                             const float* __restrict__ Y) {
    __shared__ float As[2][TK][68];
    __shared__ float Bs[2][TK][68];
    __shared__ float ynS[64];

    const int b  = blockIdx.z;
    const int i0 = blockIdx.y * 64;
    const int j0 = blockIdx.x * 64;
    const float* A = X + (size_t)b * CDIM * HW;
    const float* B = Y + (size_t)b * CDIM * HW;

    const int t  = threadIdx.x;
    const int tx = t & 15;         // micro-tile col group (j)
    const int ty = t >> 4;         // micro-tile row group (i)
    const int lr = t >> 2;         // load row (0..63)
    const int lq = t & 3;          // load k-quad (0..3)

    const float* aptr = A + (size_t)(i0 + lr) * HW + lq * 4;
    const float* bptr = B + (size_t)(j0 + lr) * HW + lq * 4;

    float ysq = 0.f;

    // preload chunk 0
    {
        float4 av = *(const float4*)(aptr);
        float4 bv = *(const float4*)(bptr);
        ysq += bv.x * bv.x + bv.y * bv.y + bv.z * bv.z + bv.w * bv.w;
        As[0][lq * 4 + 0][lr] = av.x; As[0][lq * 4 + 1][lr] = av.y;
        As[0][lq * 4 + 2][lr] = av.z; As[0][lq * 4 + 3][lr] = av.w;
        Bs[0][lq * 4 + 0][lr] = bv.x; Bs[0][lq * 4 + 1][lr] = bv.y;
        Bs[0][lq * 4 + 2][lr] = bv.z; Bs[0][lq * 4 + 3][lr] = bv.w;
    }
    __syncthreads();

    unsigned long long acc[4][2];
#pragma unroll
    for (int i = 0; i < 4; ++i) { acc[i][0] = 0ull; acc[i][1] = 0ull; }

    int p = 0;
    for (int kc = 0; kc < NK; ++kc) {
        float4 avn, bvn;
        const bool more = (kc + 1 < NK);
        if (more) {
            avn = *(const float4*)(aptr + (kc + 1) * TK);
            bvn = *(const float4*)(bptr + (kc + 1) * TK);
            ysq += bvn.x * bvn.x + bvn.y * bvn.y + bvn.z * bvn.z + bvn.w * bvn.w;
        }
#pragma unroll
        for (int k = 0; k < TK; ++k) {
            float4 a = *(const float4*)&As[p][k][ty * 4];
            float4 q = *(const float4*)&Bs[p][k][tx * 4];
            unsigned long long qa = pack2(q.x, q.y);
            unsigned long long qb = pack2(q.z, q.w);
            unsigned long long d0 = dup2(a.x), d1 = dup2(a.y), d2 = dup2(a.z), d3 = dup2(a.w);
            acc[0][0] = fma2(d0, qa, acc[0][0]); acc[0][1] = fma2(d0, qb, acc[0][1]);
            acc[1][0] = fma2(d1, qa, acc[1][0]); acc[1][1] = fma2(d1, qb, acc[1][1]);
            acc[2][0] = fma2(d2, qa, acc[2][0]); acc[2][1] = fma2(d2, qb, acc[2][1]);
            acc[3][0] = fma2(d3, qa, acc[3][0]); acc[3][1] = fma2(d3, qb, acc[3][1]);
        }
        if (more) {
            int np = p ^ 1;
            As[np][lq * 4 + 0][lr] = avn.x; As[np][lq * 4 + 1][lr] = avn.y;
            As[np][lq * 4 + 2][lr] = avn.z; As[np][lq * 4 + 3][lr] = avn.w;
            Bs[np][lq * 4 + 0][lr] = bvn.x; Bs[np][lq * 4 + 1][lr] = bvn.y;
            Bs[np][lq * 4 + 2][lr] = bvn.z; Bs[np][lq * 4 + 3][lr] = bvn.w;
        }
        __syncthreads();
        p ^= 1;
    }

    // ynorm: reduce ysq across the 4 lanes sharing lr (lanes lr*4 + {0..3})
    ysq += __shfl_down_sync(0xffffffffu, ysq, 2);
    ysq += __shfl_down_sync(0xffffffffu, ysq, 1);
    if (lq == 0) ynS[lr] = ysq;
    __syncthreads();

    // epilogue: per-row argmin, tie -> lower j (matches jnp.argmin)
    float yn0 = ynS[tx * 4 + 0], yn1 = ynS[tx * 4 + 1];
    float yn2 = ynS[tx * 4 + 2], yn3 = ynS[tx * 4 + 3];
#pragma unroll
    for (int ii = 0; ii < 4; ++ii) {
        float2 d01 = unpack2(acc[ii][0]);
        float2 d23 = unpack2(acc[ii][1]);
        float d0 = yn0 - 2.f * d01.x;
        float d1 = yn1 - 2.f * d01.y;
        float d2 = yn2 - 2.f * d23.x;
        float d3 = yn3 - 2.f * d23.y;
        float bvv = d0; int bj = j0 + tx * 4;
        if (d1 < bvv) { bvv = d1; bj = j0 + tx * 4 + 1; }
        if (d2 < bvv) { bvv = d2; bj = j0 + tx * 4 + 2; }
        if (d3 < bvv) { bvv = d3; bj = j0 + tx * 4 + 3; }
        // reduce over the 16 lanes sharing ty (segments of width 16)
#pragma unroll
        for (int o = 8; o; o >>= 1) {
            float ov = __shfl_down_sync(0xffffffffu, bvv, o, 16);
            int   oj = __shfl_down_sync(0xffffffffu, bj,  o, 16);
            if (ov < bvv || (ov == bvv && oj < bj)) { bvv = ov; bj = oj; }
        }
        if (tx == 0) {
            unsigned u = __float_as_uint(bvv);
            u = (u & 0x80000000u) ? ~u : (u | 0x80000000u);  // orderable encoding
            unsigned long long key = ((unsigned long long)u << 32) | (unsigned)bj;
            atomicMin(&g_best[b * CDIM + i0 + ty * 4 + ii], key);
        }
    }
}

// ---------------------------------------------------------------------------
// 2) gather: out[b,i,:] = Y[b, best_idx[b,i], :]
// ---------------------------------------------------------------------------
__global__ void __launch_bounds__(256) gather_kernel(const float* __restrict__ Y,
                                                     float* __restrict__ out) {
    int row  = blockIdx.x >> 2;   // b*CDIM + i
    int part = blockIdx.x & 3;
    int b    = row >> 8;
    int src  = (int)(unsigned)(g_best[row] & 0xffffffffull);
    const float4* yp = (const float4*)(Y + ((size_t)(b * CDIM + src)) * HW);
    float4*       op = (float4*)(out + (size_t)row * HW);
    int e = part * 256 + threadIdx.x;   // 1024 float4 per row
    op[e] = yp[e];
}

// ---------------------------------------------------------------------------
extern "C" void kernel_launch(void* const* d_in, const int* in_sizes, int n_in,
                              void* d_out, int out_size) {
    const float* x = (const float*)d_in[0];
    const float* y = (const float*)d_in[1];
    float* out = (float*)d_out;

    init_kernel<<<BATCH * CDIM / 256, 256>>>();

    dim3 g(CDIM / 64, CDIM / 64, BATCH);   // 4 x 4 x 16 = 256 CTAs
    gemm_argmin_kernel<<<g, 256>>>(x, y);

    gather_kernel<<<BATCH * CDIM * 4, 256>>>(y, out);
}

// round 4
// speedup vs baseline: 1.8307x; 1.4824x over previous
#include <cuda_runtime.h>
#include <cuda_bf16.h>
#include <stdint.h>

#define BATCH 16
#define CDIM 256
#define HW 4096
#define KC 32                 // k-chunk (bf16 elems)
#define NKC (HW / KC)         // 128
#define SSTR 40               // smem row stride in bf16 (80B, 16B-aligned, 8-row bank period)
#define TAU 4.0f

__device__ float g_dist[BATCH * CDIM * CDIM];   // 4 MB approx dist^2
__device__ int   g_idx[BATCH * CDIM];

// ---------------- helpers ----------------
__device__ __forceinline__ uint32_t bf2(float x, float y) {
    __nv_bfloat162 h = __floats2bfloat162_rn(x, y);
    return *reinterpret_cast<uint32_t*>(&h);
}
__device__ __forceinline__ float2 bf2f(uint32_t u) {
    __nv_bfloat162 h = *reinterpret_cast<__nv_bfloat162*>(&u);
    return __bfloat1622float2(h);
}
__device__ __forceinline__ uint32_t smaddr(const void* p) {
    return (uint32_t)__cvta_generic_to_shared(p);
}
__device__ __forceinline__ void ldsm4(uint32_t a, uint32_t* r) {
    asm volatile("ldmatrix.sync.aligned.m8n8.x4.shared.b16 {%0,%1,%2,%3}, [%4];"
                 : "=r"(r[0]), "=r"(r[1]), "=r"(r[2]), "=r"(r[3]) : "r"(a));
}
__device__ __forceinline__ void mma_bf16(float* d, const uint32_t* a, const uint32_t* b) {
    asm volatile("mma.sync.aligned.m16n8k16.row.col.f32.bf16.bf16.f32 "
                 "{%0,%1,%2,%3}, {%4,%5,%6,%7}, {%8,%9}, {%0,%1,%2,%3};"
                 : "+f"(d[0]), "+f"(d[1]), "+f"(d[2]), "+f"(d[3])
                 : "r"(a[0]), "r"(a[1]), "r"(a[2]), "r"(a[3]), "r"(b[0]), "r"(b[1]));
}

// convert 16 floats (4 float4) -> hi/lo bf16 pairs, store 2+2 uint4 to smem
__device__ __forceinline__ void cvt_store(__nv_bfloat16* dh, __nv_bfloat16* dl,
                                          const float4* v) {
    uint4 hi0, hi1, lo0, lo1;
#define CVT1(HI, LO, F)                                        \
    { HI = bf2((F).x, (F).y); float2 _f = bf2f(HI);            \
      LO = bf2((F).x - _f.x, (F).y - _f.y); }
#define CVT2(HI, LO, F)                                        \
    { HI = bf2((F).z, (F).w); float2 _f = bf2f(HI);            \
      LO = bf2((F).z - _f.x, (F).w - _f.y); }
    CVT1(hi0.x, lo0.x, v[0]); CVT2(hi0.y, lo0.y, v[0]);
    CVT1(hi0.z, lo0.z, v[1]); CVT2(hi0.w, lo0.w, v[1]);
    CVT1(hi1.x, lo1.x, v[2]); CVT2(hi1.y, lo1.y, v[2]);
    CVT1(hi1.z, lo1.z, v[3]); CVT2(hi1.w, lo1.w, v[3]);
#undef CVT1
#undef CVT2
    ((uint4*)dh)[0] = hi0; ((uint4*)dh)[1] = hi1;
    ((uint4*)dl)[0] = lo0; ((uint4*)dl)[1] = lo1;
}

// ---------------------------------------------------------------------------
// 1) approx dist^2 via bf16 hi/lo split tensor MMA.
//    CTA: 64(i) x 64(j), 128 threads (4 warps, 32x32 warp tiles).
// ---------------------------------------------------------------------------
__global__ void __launch_bounds__(128) gemm_bf16_kernel(const float* __restrict__ X,
                                                        const float* __restrict__ Y) {
    __shared__ __nv_bfloat16 sAh[2 * 64 * SSTR];
    __shared__ __nv_bfloat16 sAl[2 * 64 * SSTR];
    __shared__ __nv_bfloat16 sBh[2 * 64 * SSTR];
    __shared__ __nv_bfloat16 sBl[2 * 64 * SSTR];
    __shared__ float ynS[64];

    const int b  = blockIdx.z;
    const int i0 = blockIdx.y * 64;
    const int j0 = blockIdx.x * 64;
    const int t  = threadIdx.x;

    // loader mapping: row r = t>>1, half h = t&1 (16 floats each)
    const int r = t >> 1, h = t & 1;
    const float* aRow = X + (size_t)(b * CDIM + i0 + r) * HW + h * 16;
    const float* bRow = Y + (size_t)(b * CDIM + j0 + r) * HW + h * 16;
    const int soff = r * SSTR + h * 16;

    float ysq = 0.f;
    float4 av[4], bv[4];

    // prologue: chunk 0
#pragma unroll
    for (int q = 0; q < 4; ++q) {
        av[q] = ((const float4*)aRow)[q];
        bv[q] = ((const float4*)bRow)[q];
        ysq += bv[q].x * bv[q].x + bv[q].y * bv[q].y + bv[q].z * bv[q].z + bv[q].w * bv[q].w;
    }
    cvt_store(sAh + soff, sAl + soff, av);
    cvt_store(sBh + soff, sBl + soff, bv);
    __syncthreads();

    // warp tiling
    const int lane = t & 31;
    const int w    = t >> 5;
    const int i0w  = (w >> 1) * 32;
    const int j0w  = (w & 1) * 32;
    const int arow = i0w + (lane & 15);
    const int acol = (lane >> 4) * 8;                        // +8 bf16 for lanes 16-31
    const int bn   = j0w + (lane & 7) + ((lane >> 4) << 3);  // n row
    const int bk   = ((lane >> 3) & 1) * 8;                  // +8 bf16 for k8 groups

    float acc[2][4][4];
#pragma unroll
    for (int m = 0; m < 2; ++m)
#pragma unroll
        for (int n = 0; n < 4; ++n)
#pragma unroll
            for (int e = 0; e < 4; ++e) acc[m][n][e] = 0.f;

    int p = 0;
    for (int kc = 0; kc < NKC; ++kc) {
        const bool more = (kc + 1 < NKC);
        if (more) {
#pragma unroll
            for (int q = 0; q < 4; ++q) {
                av[q] = ((const float4*)(aRow + (kc + 1) * KC))[q];
                bv[q] = ((const float4*)(bRow + (kc + 1) * KC))[q];
                ysq += bv[q].x * bv[q].x + bv[q].y * bv[q].y + bv[q].z * bv[q].z + bv[q].w * bv[q].w;
            }
        }

        const int pb = p * 64 * SSTR;
#pragma unroll
        for (int s = 0; s < 2; ++s) {   // two k16 steps per chunk
            uint32_t ah[2][4], al[2][4], bh[2][4], bl[2][4];
            const int akoff = pb + arow * SSTR + s * 16 + acol;
            ldsm4(smaddr(sAh + akoff), ah[0]);
            ldsm4(smaddr(sAh + akoff + 16 * SSTR), ah[1]);
            ldsm4(smaddr(sAl + akoff), al[0]);
            ldsm4(smaddr(sAl + akoff + 16 * SSTR), al[1]);
            const int bkoff = pb + bn * SSTR + s * 16 + bk;
            ldsm4(smaddr(sBh + bkoff), bh[0]);
            ldsm4(smaddr(sBh + bkoff + 16 * SSTR), bh[1]);
            ldsm4(smaddr(sBl + bkoff), bl[0]);
            ldsm4(smaddr(sBl + bkoff + 16 * SSTR), bl[1]);
#pragma unroll
            for (int mb = 0; mb < 2; ++mb) {
#pragma unroll
                for (int nb = 0; nb < 4; ++nb) {
                    const uint32_t* bhf = (nb < 2 ? bh[0] : bh[1]) + (nb & 1) * 2;
                    const uint32_t* blf = (nb < 2 ? bl[0] : bl[1]) + (nb & 1) * 2;
                    mma_bf16(acc[mb][nb], ah[mb], bhf);   // hi*hi
                    mma_bf16(acc[mb][nb], ah[mb], blf);   // hi*lo
                    mma_bf16(acc[mb][nb], al[mb], bhf);   // lo*hi
                }
            }
        }

        if (more) {
            const int nb = (p ^ 1) * 64 * SSTR + soff;
            cvt_store(sAh + nb, sAl + nb, av);
            cvt_store(sBh + nb, sBl + nb, bv);
        }
        __syncthreads();
        p ^= 1;
    }

    // ynorm (fp32 exact): pair-reduce halves
    ysq += __shfl_xor_sync(0xffffffffu, ysq, 1);
    if (h == 0) ynS[r] = ysq;
    __syncthreads();

    // epilogue: dist = yn[j] - 2*dot
#pragma unroll
    for (int mb = 0; mb < 2; ++mb) {
#pragma unroll
        for (int nb = 0; nb < 4; ++nb) {
            const int jc = j0w + nb * 8 + (lane & 3) * 2;
            float2 yn = *(float2*)&ynS[jc];
            const int grow = b * CDIM + i0 + i0w + mb * 16 + (lane >> 2);
            float2 d0, d1;
            d0.x = yn.x - 2.f * acc[mb][nb][0];
            d0.y = yn.y - 2.f * acc[mb][nb][1];
            d1.x = yn.x - 2.f * acc[mb][nb][2];
            d1.y = yn.y - 2.f * acc[mb][nb][3];
            *(float2*)&g_dist[(size_t)grow * CDIM + j0 + jc] = d0;
            *(float2*)&g_dist[(size_t)(grow + 8) * CDIM + j0 + jc] = d1;
        }
    }
}

// ---------------------------------------------------------------------------
// 2) argmin with exact-fp32 rescue of near-ties. One block per row.
// ---------------------------------------------------------------------------
__global__ void __launch_bounds__(256) rescore_kernel(const float* __restrict__ X,
                                                      const float* __restrict__ Y) {
    const int row = blockIdx.x;           // b*CDIM + i
    const int b   = row >> 8;
    const int t   = threadIdx.x;

    __shared__ float s_red[8];
    __shared__ float s_minv;
    __shared__ int   s_cnt;
    __shared__ int   s_lst[256];

    float d = g_dist[(size_t)row * CDIM + t];

    // block min of approx dist
    float v = d;
#pragma unroll
    for (int o = 16; o; o >>= 1) v = fminf(v, __shfl_down_sync(0xffffffffu, v, o));
    if ((t & 31) == 0) s_red[t >> 5] = v;
    __syncthreads();
    if (t == 0) {
        float m = s_red[0];
#pragma unroll
        for (int i = 1; i < 8; ++i) m = fminf(m, s_red[i]);
        s_minv = m;
        s_cnt = 0;
    }
    __syncthreads();

    if (d <= s_minv + TAU) {
        int pos = atomicAdd(&s_cnt, 1);
        s_lst[pos] = t;
    }
    __syncthreads();

    const int n = s_cnt;
    if (n == 1) {
        if (t == 0) g_idx[row] = s_lst[0];
        return;
    }

    // exact fp32 rescore of all candidates; tie -> lower j
    const float* xr = X + (size_t)row * HW;
    float bestv = 3.4e38f;
    int   bestj = 0x7fffffff;
    for (int c = 0; c < n; ++c) {
        const int j = s_lst[c];
        const float* yr = Y + (size_t)(b * CDIM + j) * HW;
        float s = 0.f;
#pragma unroll
        for (int q = 0; q < 4; ++q) {
            float4 xv = ((const float4*)xr)[t + q * 256];
            float4 yv = ((const float4*)yr)[t + q * 256];
            float dx = xv.x - yv.x, dy = xv.y - yv.y, dz = xv.z - yv.z, dw = xv.w - yv.w;
            s += dx * dx + dy * dy + dz * dz + dw * dw;
        }
#pragma unroll
        for (int o = 16; o; o >>= 1) s += __shfl_down_sync(0xffffffffu, s, o);
        if ((t & 31) == 0) s_red[t >> 5] = s;
        __syncthreads();
        if (t == 0) {
            float tot = 0.f;
#pragma unroll
            for (int i = 0; i < 8; ++i) tot += s_red[i];
            if (tot < bestv || (tot == bestv && j < bestj)) { bestv = tot; bestj = j; }
        }
        __syncthreads();
    }
    if (t == 0) g_idx[row] = bestj;
}

// ---------------------------------------------------------------------------
// 3) gather: out[b,i,:] = Y[b, g_idx[b,i], :]
// ---------------------------------------------------------------------------
__global__ void __launch_bounds__(256) gather_kernel(const float* __restrict__ Y,
                                                     float* __restrict__ out) {
    int row  = blockIdx.x >> 2;   // b*CDIM + i
    int part = blockIdx.x & 3;
    int bb   = row >> 8;
    int src  = g_idx[row];
    const float4* yp = (const float4*)(Y + (size_t)(bb * CDIM + src) * HW);
    float4*       op = (float4*)(out + (size_t)row * HW);
    int e = part * 256 + threadIdx.x;
    op[e] = yp[e];
}

// ---------------------------------------------------------------------------
extern "C" void kernel_launch(void* const* d_in, const int* in_sizes, int n_in,
                              void* d_out, int out_size) {
    const float* x = (const float*)d_in[0];
    const float* y = (const float*)d_in[1];
    float* out = (float*)d_out;

    dim3 g(CDIM / 64, CDIM / 64, BATCH);   // 4 x 4 x 16 = 256 CTAs
    gemm_bf16_kernel<<<g, 128>>>(x, y);

    rescore_kernel<<<BATCH * CDIM, 256>>>(x, y);

    gather_kernel<<<BATCH * CDIM * 4, 256>>>(y, out);
}

// round 5
// speedup vs baseline: 2.2635x; 1.2364x over previous
#include <cuda_runtime.h>
#include <cuda_bf16.h>
#include <stdint.h>

#define BATCH 16
#define CDIM 256
#define HW 4096
#define KC 32                 // k-chunk (bf16 elems)
#define NKC (HW / KC)         // 128
#define SSTR 40               // smem row stride in bf16 (80B; 8-row bank period)
#define TAU 8.0f

__device__ float g_dist[BATCH * CDIM * CDIM];   // 4 MB approx dist^2
__device__ int   g_idx[BATCH * CDIM];

// ---------------- helpers ----------------
__device__ __forceinline__ uint32_t bf2(float x, float y) {
    __nv_bfloat162 h = __floats2bfloat162_rn(x, y);
    return *reinterpret_cast<uint32_t*>(&h);
}
__device__ __forceinline__ uint32_t smaddr(const void* p) {
    return (uint32_t)__cvta_generic_to_shared(p);
}
__device__ __forceinline__ void ldsm4(uint32_t a, uint32_t* r) {
    asm volatile("ldmatrix.sync.aligned.m8n8.x4.shared.b16 {%0,%1,%2,%3}, [%4];"
                 : "=r"(r[0]), "=r"(r[1]), "=r"(r[2]), "=r"(r[3]) : "r"(a));
}
__device__ __forceinline__ void mma_bf16(float* d, const uint32_t* a, const uint32_t* b) {
    asm volatile("mma.sync.aligned.m16n8k16.row.col.f32.bf16.bf16.f32 "
                 "{%0,%1,%2,%3}, {%4,%5,%6,%7}, {%8,%9}, {%0,%1,%2,%3};"
                 : "+f"(d[0]), "+f"(d[1]), "+f"(d[2]), "+f"(d[3])
                 : "r"(a[0]), "r"(a[1]), "r"(a[2]), "r"(a[3]), "r"(b[0]), "r"(b[1]));
}
// 16 floats -> 16 bf16 (round-to-nearest), two 16B stores
__device__ __forceinline__ void cvt_store_hi(__nv_bfloat16* d, const float4* v) {
    uint4 o0, o1;
    o0.x = bf2(v[0].x, v[0].y); o0.y = bf2(v[0].z, v[0].w);
    o0.z = bf2(v[1].x, v[1].y); o0.w = bf2(v[1].z, v[1].w);
    o1.x = bf2(v[2].x, v[2].y); o1.y = bf2(v[2].z, v[2].w);
    o1.z = bf2(v[3].x, v[3].y); o1.w = bf2(v[3].z, v[3].w);
    ((uint4*)d)[0] = o0; ((uint4*)d)[1] = o1;
}

// ---------------------------------------------------------------------------
// 1) approx dist^2 = |y_j|^2 - 2*x_i.y_j via bf16(hi) tensor MMA.
//    CTA: 64(i) x 64(j), 256 threads, 8 warps in 4(i) x 2(j), warp tile 16x32.
// ---------------------------------------------------------------------------
__global__ void __launch_bounds__(256) gemm_bf16_kernel(const float* __restrict__ X,
                                                        const float* __restrict__ Y) {
    __shared__ __nv_bfloat16 sAh[2 * 64 * SSTR];
    __shared__ __nv_bfloat16 sBh[2 * 64 * SSTR];
    __shared__ float ynS[64];

    const int b  = blockIdx.z;
    const int i0 = blockIdx.y * 64;
    const int j0 = blockIdx.x * 64;
    const int t  = threadIdx.x;

    // loader: threads 0-127 -> A rows, 128-255 -> B rows; 16 floats each/chunk
    const bool isB = t >= 128;
    const int r = (t & 127) >> 1, h = t & 1;
    const float* srcRow = (isB ? Y + (size_t)(b * CDIM + j0 + r) * HW
                               : X + (size_t)(b * CDIM + i0 + r) * HW) + h * 16;
    __nv_bfloat16* dst = (isB ? sBh : sAh) + r * SSTR + h * 16;

    float ysq = 0.f;
    float4 v[4];

    // prologue: chunk 0
#pragma unroll
    for (int q = 0; q < 4; ++q) {
        v[q] = ((const float4*)srcRow)[q];
        if (isB) ysq += v[q].x * v[q].x + v[q].y * v[q].y + v[q].z * v[q].z + v[q].w * v[q].w;
    }
    cvt_store_hi(dst, v);
    __syncthreads();

    // warp tiling: 8 warps = 4(i) x 2(j); warp tile 16(m) x 32(n)
    const int lane = t & 31;
    const int w    = t >> 5;
    const int i0w  = (w >> 1) * 16;
    const int j0w  = (w & 1) * 32;
    const int arow = i0w + (lane & 15);
    const int acol = (lane >> 4) * 8;
    const int bn   = j0w + (lane & 7) + ((lane >> 4) << 3);
    const int bk   = ((lane >> 3) & 1) * 8;

    float acc[4][4];
#pragma unroll
    for (int n = 0; n < 4; ++n)
#pragma unroll
        for (int e = 0; e < 4; ++e) acc[n][e] = 0.f;

    int p = 0;
    for (int kc = 0; kc < NKC; ++kc) {
        const bool more = (kc + 1 < NKC);
        if (more) {
#pragma unroll
            for (int q = 0; q < 4; ++q) {
                v[q] = ((const float4*)(srcRow + (kc + 1) * KC))[q];
                if (isB) ysq += v[q].x * v[q].x + v[q].y * v[q].y + v[q].z * v[q].z + v[q].w * v[q].w;
            }
        }

        const int pb = p * 64 * SSTR;
#pragma unroll
        for (int s = 0; s < 2; ++s) {   // two k16 steps per chunk
            uint32_t ah[4], bh0[4], bh1[4];
            ldsm4(smaddr(sAh + pb + arow * SSTR + s * 16 + acol), ah);
            const int bkoff = pb + bn * SSTR + s * 16 + bk;
            ldsm4(smaddr(sBh + bkoff), bh0);
            ldsm4(smaddr(sBh + bkoff + 16 * SSTR), bh1);
            mma_bf16(acc[0], ah, bh0);
            mma_bf16(acc[1], ah, bh0 + 2);
            mma_bf16(acc[2], ah, bh1);
            mma_bf16(acc[3], ah, bh1 + 2);
        }

        if (more) cvt_store_hi(dst + (p ^ 1) * 64 * SSTR, v);
        __syncthreads();
        p ^= 1;
    }

    // ynorm (fp32 exact) from B loaders: pair-reduce halves
    ysq += __shfl_xor_sync(0xffffffffu, ysq, 1);
    if (isB && h == 0) ynS[r] = ysq;
    __syncthreads();

    // epilogue: dist = yn[j] - 2*dot
#pragma unroll
    for (int nb = 0; nb < 4; ++nb) {
        const int jc = j0w + nb * 8 + (lane & 3) * 2;
        float2 yn = *(float2*)&ynS[jc];
        const int grow = b * CDIM + i0 + i0w + (lane >> 2);
        float2 d0, d1;
        d0.x = yn.x - 2.f * acc[nb][0];
        d0.y = yn.y - 2.f * acc[nb][1];
        d1.x = yn.x - 2.f * acc[nb][2];
        d1.y = yn.y - 2.f * acc[nb][3];
        *(float2*)&g_dist[(size_t)grow * CDIM + j0 + jc] = d0;
        *(float2*)&g_dist[(size_t)(grow + 8) * CDIM + j0 + jc] = d1;
    }
}

// ---------------------------------------------------------------------------
// 2) argmin with exact-fp32 rescue of near-ties. One block per row.
// ---------------------------------------------------------------------------
__global__ void __launch_bounds__(256) rescore_kernel(const float* __restrict__ X,
                                                      const float* __restrict__ Y) {
    const int row = blockIdx.x;           // b*CDIM + i
    const int b   = row >> 8;
    const int t   = threadIdx.x;

    __shared__ float s_red[8];
    __shared__ float s_minv;
    __shared__ int   s_cnt;
    __shared__ int   s_lst[256];

    float d = g_dist[(size_t)row * CDIM + t];

    float vv = d;
#pragma unroll
    for (int o = 16; o; o >>= 1) vv = fminf(vv, __shfl_down_sync(0xffffffffu, vv, o));
    if ((t & 31) == 0) s_red[t >> 5] = vv;
    __syncthreads();
    if (t == 0) {
        float m = s_red[0];
#pragma unroll
        for (int i = 1; i < 8; ++i) m = fminf(m, s_red[i]);
        s_minv = m;
        s_cnt = 0;
    }
    __syncthreads();

    if (d <= s_minv + TAU) {
        int pos = atomicAdd(&s_cnt, 1);
        s_lst[pos] = t;
    }
    __syncthreads();

    const int n = s_cnt;
    if (n == 1) {
        if (t == 0) g_idx[row] = s_lst[0];
        return;
    }

    // exact fp32 rescore; tie -> lower j
    const float* xr = X + (size_t)row * HW;
    float bestv = 3.4e38f;
    int   bestj = 0x7fffffff;
    for (int c = 0; c < n; ++c) {
        const int j = s_lst[c];
        const float* yr = Y + (size_t)(b * CDIM + j) * HW;
        float s = 0.f;
#pragma unroll
        for (int q = 0; q < 4; ++q) {
            float4 xv = ((const float4*)xr)[t + q * 256];
            float4 yv = ((const float4*)yr)[t + q * 256];
            float dx = xv.x - yv.x, dy = xv.y - yv.y, dz = xv.z - yv.z, dw = xv.w - yv.w;
            s += dx * dx + dy * dy + dz * dz + dw * dw;
        }
#pragma unroll
        for (int o = 16; o; o >>= 1) s += __shfl_down_sync(0xffffffffu, s, o);
        if ((t & 31) == 0) s_red[t >> 5] = s;
        __syncthreads();
        if (t == 0) {
            float tot = 0.f;
#pragma unroll
            for (int i = 0; i < 8; ++i) tot += s_red[i];
            if (tot < bestv || (tot == bestv && j < bestj)) { bestv = tot; bestj = j; }
        }
        __syncthreads();
    }
    if (t == 0) g_idx[row] = bestj;
}

// ---------------------------------------------------------------------------
// 3) gather: out[b,i,:] = Y[b, g_idx[b,i], :]
// ---------------------------------------------------------------------------
__global__ void __launch_bounds__(256) gather_kernel(const float* __restrict__ Y,
                                                     float* __restrict__ out) {
    int row  = blockIdx.x >> 2;
    int part = blockIdx.x & 3;
    int bb   = row >> 8;
    int src  = g_idx[row];
    const float4* yp = (const float4*)(Y + (size_t)(bb * CDIM + src) * HW);
    float4*       op = (float4*)(out + (size_t)row * HW);
    int e = part * 256 + threadIdx.x;
    op[e] = yp[e];
}

// ---------------------------------------------------------------------------
extern "C" void kernel_launch(void* const* d_in, const int* in_sizes, int n_in,
                              void* d_out, int out_size) {
    const float* x = (const float*)d_in[0];
    const float* y = (const float*)d_in[1];
    float* out = (float*)d_out;

    dim3 g(CDIM / 64, CDIM / 64, BATCH);   // 4 x 4 x 16 = 256 CTAs
    gemm_bf16_kernel<<<g, 256>>>(x, y);

    rescore_kernel<<<BATCH * CDIM, 256>>>(x, y);

    gather_kernel<<<BATCH * CDIM * 4, 256>>>(y, out);
}

// round 6
// speedup vs baseline: 2.8863x; 1.2752x over previous
#include <cuda_runtime.h>
#include <cuda_bf16.h>
#include <stdint.h>

#define BATCH 16
#define CDIM 256
#define HW 4096
#define KC 32                 // k-chunk (bf16 elems)
#define KSPLIT 4
#define KSEG (HW / KSPLIT)    // 1024
#define NKCS (KSEG / KC)      // 32 chunks per CTA
#define SSTR 40               // smem row stride in bf16 (80B; 8-row bank period)
#define TAU 8.0f

__device__ float g_part[KSPLIT][BATCH * CDIM * CDIM];   // 16 MB partial dist
__device__ int   g_idx[BATCH * CDIM];

// ---------------- helpers ----------------
__device__ __forceinline__ uint32_t bf2(float x, float y) {
    __nv_bfloat162 h = __floats2bfloat162_rn(x, y);
    return *reinterpret_cast<uint32_t*>(&h);
}
__device__ __forceinline__ uint32_t smaddr(const void* p) {
    return (uint32_t)__cvta_generic_to_shared(p);
}
__device__ __forceinline__ void ldsm4(uint32_t a, uint32_t* r) {
    asm volatile("ldmatrix.sync.aligned.m8n8.x4.shared.b16 {%0,%1,%2,%3}, [%4];"
                 : "=r"(r[0]), "=r"(r[1]), "=r"(r[2]), "=r"(r[3]) : "r"(a));
}
__device__ __forceinline__ void mma_bf16(float* d, const uint32_t* a, const uint32_t* b) {
    asm volatile("mma.sync.aligned.m16n8k16.row.col.f32.bf16.bf16.f32 "
                 "{%0,%1,%2,%3}, {%4,%5,%6,%7}, {%8,%9}, {%0,%1,%2,%3};"
                 : "+f"(d[0]), "+f"(d[1]), "+f"(d[2]), "+f"(d[3])
                 : "r"(a[0]), "r"(a[1]), "r"(a[2]), "r"(a[3]), "r"(b[0]), "r"(b[1]));
}
__device__ __forceinline__ void cvt_store_hi(__nv_bfloat16* d, const float4* v) {
    uint4 o0, o1;
    o0.x = bf2(v[0].x, v[0].y); o0.y = bf2(v[0].z, v[0].w);
    o0.z = bf2(v[1].x, v[1].y); o0.w = bf2(v[1].z, v[1].w);
    o1.x = bf2(v[2].x, v[2].y); o1.y = bf2(v[2].z, v[2].w);
    o1.z = bf2(v[3].x, v[3].y); o1.w = bf2(v[3].z, v[3].w);
    ((uint4*)d)[0] = o0; ((uint4*)d)[1] = o1;
}

// ---------------------------------------------------------------------------
// 1) partial dist^2 over one k-segment: |y|^2_seg - 2*dot_seg (bf16 hi MMA).
//    CTA: 64(i) x 64(j) x kseg, 256 threads, 8 warps 4(i)x2(j), wtile 16x32.
// ---------------------------------------------------------------------------
__global__ void __launch_bounds__(256) gemm_bf16_kernel(const float* __restrict__ X,
                                                        const float* __restrict__ Y) {
    __shared__ __nv_bfloat16 sAh[2 * 64 * SSTR];
    __shared__ __nv_bfloat16 sBh[2 * 64 * SSTR];
    __shared__ float ynS[64];

    const int b  = blockIdx.z >> 2;
    const int ks = blockIdx.z & 3;
    const int i0 = blockIdx.y * 64;
    const int j0 = blockIdx.x * 64;
    const int t  = threadIdx.x;

    // loader: threads 0-127 -> A rows, 128-255 -> B rows; 16 floats each/chunk
    const bool isB = t >= 128;
    const int r = (t & 127) >> 1, h = t & 1;
    const float* srcRow = (isB ? Y + (size_t)(b * CDIM + j0 + r) * HW
                               : X + (size_t)(b * CDIM + i0 + r) * HW) + ks * KSEG + h * 16;
    __nv_bfloat16* dst = (isB ? sBh : sAh) + r * SSTR + h * 16;

    float ysq = 0.f;
    float4 v[4];

#pragma unroll
    for (int q = 0; q < 4; ++q) {
        v[q] = ((const float4*)srcRow)[q];
        if (isB) ysq += v[q].x * v[q].x + v[q].y * v[q].y + v[q].z * v[q].z + v[q].w * v[q].w;
    }
    cvt_store_hi(dst, v);
    __syncthreads();

    const int lane = t & 31;
    const int w    = t >> 5;
    const int i0w  = (w >> 1) * 16;
    const int j0w  = (w & 1) * 32;
    const int arow = i0w + (lane & 15);
    const int acol = (lane >> 4) * 8;
    const int bn   = j0w + (lane & 7) + ((lane >> 4) << 3);
    const int bk   = ((lane >> 3) & 1) * 8;

    float acc[4][4];
#pragma unroll
    for (int n = 0; n < 4; ++n)
#pragma unroll
        for (int e = 0; e < 4; ++e) acc[n][e] = 0.f;

    int p = 0;
    for (int kc = 0; kc < NKCS; ++kc) {
        const bool more = (kc + 1 < NKCS);
        if (more) {
#pragma unroll
            for (int q = 0; q < 4; ++q) {
                v[q] = ((const float4*)(srcRow + (kc + 1) * KC))[q];
                if (isB) ysq += v[q].x * v[q].x + v[q].y * v[q].y + v[q].z * v[q].z + v[q].w * v[q].w;
            }
        }

        const int pb = p * 64 * SSTR;
#pragma unroll
        for (int s = 0; s < 2; ++s) {
            uint32_t ah[4], bh0[4], bh1[4];
            ldsm4(smaddr(sAh + pb + arow * SSTR + s * 16 + acol), ah);
            const int bkoff = pb + bn * SSTR + s * 16 + bk;
            ldsm4(smaddr(sBh + bkoff), bh0);
            ldsm4(smaddr(sBh + bkoff + 16 * SSTR), bh1);
            mma_bf16(acc[0], ah, bh0);
            mma_bf16(acc[1], ah, bh0 + 2);
            mma_bf16(acc[2], ah, bh1);
            mma_bf16(acc[3], ah, bh1 + 2);
        }

        if (more) cvt_store_hi(dst + (p ^ 1) * 64 * SSTR, v);
        __syncthreads();
        p ^= 1;
    }

    // partial ynorm (fp32 exact over this k-segment)
    ysq += __shfl_xor_sync(0xffffffffu, ysq, 1);
    if (isB && h == 0) ynS[r] = ysq;
    __syncthreads();

    float* gout = g_part[ks];
#pragma unroll
    for (int nb = 0; nb < 4; ++nb) {
        const int jc = j0w + nb * 8 + (lane & 3) * 2;
        float2 yn = *(float2*)&ynS[jc];
        const int grow = b * CDIM + i0 + i0w + (lane >> 2);
        float2 d0, d1;
        d0.x = yn.x - 2.f * acc[nb][0];
        d0.y = yn.y - 2.f * acc[nb][1];
        d1.x = yn.x - 2.f * acc[nb][2];
        d1.y = yn.y - 2.f * acc[nb][3];
        *(float2*)&gout[(size_t)grow * CDIM + j0 + jc] = d0;
        *(float2*)&gout[(size_t)(grow + 8) * CDIM + j0 + jc] = d1;
    }
}

// ---------------------------------------------------------------------------
// 2) argmin (sum of 4 partials) with exact-fp32 rescue. One block per row.
// ---------------------------------------------------------------------------
__global__ void __launch_bounds__(256) rescore_kernel(const float* __restrict__ X,
                                                      const float* __restrict__ Y) {
    const int row = blockIdx.x;           // b*CDIM + i
    const int b   = row >> 8;
    const int t   = threadIdx.x;

    __shared__ float s_red[8];
    __shared__ float s_minv;
    __shared__ int   s_cnt;
    __shared__ int   s_lst[256];

    const size_t off = (size_t)row * CDIM + t;
    float d = g_part[0][off] + g_part[1][off] + g_part[2][off] + g_part[3][off];

    float vv = d;
#pragma unroll
    for (int o = 16; o; o >>= 1) vv = fminf(vv, __shfl_down_sync(0xffffffffu, vv, o));
    if ((t & 31) == 0) s_red[t >> 5] = vv;
    __syncthreads();
    if (t == 0) {
        float m = s_red[0];
#pragma unroll
        for (int i = 1; i < 8; ++i) m = fminf(m, s_red[i]);
        s_minv = m;
        s_cnt = 0;
    }
    __syncthreads();

    if (d <= s_minv + TAU) {
        int pos = atomicAdd(&s_cnt, 1);
        s_lst[pos] = t;
    }
    __syncthreads();

    const int n = s_cnt;
    if (n == 1) {
        if (t == 0) g_idx[row] = s_lst[0];
        return;
    }

    const float* xr = X + (size_t)row * HW;
    float bestv = 3.4e38f;
    int   bestj = 0x7fffffff;
    for (int c = 0; c < n; ++c) {
        const int j = s_lst[c];
        const float* yr = Y + (size_t)(b * CDIM + j) * HW;
        float s = 0.f;
#pragma unroll
        for (int q = 0; q < 4; ++q) {
            float4 xv = ((const float4*)xr)[t + q * 256];
            float4 yv = ((const float4*)yr)[t + q * 256];
            float dx = xv.x - yv.x, dy = xv.y - yv.y, dz = xv.z - yv.z, dw = xv.w - yv.w;
            s += dx * dx + dy * dy + dz * dz + dw * dw;
        }
#pragma unroll
        for (int o = 16; o; o >>= 1) s += __shfl_down_sync(0xffffffffu, s, o);
        if ((t & 31) == 0) s_red[t >> 5] = s;
        __syncthreads();
        if (t == 0) {
            float tot = 0.f;
#pragma unroll
            for (int i = 0; i < 8; ++i) tot += s_red[i];
            if (tot < bestv || (tot == bestv && j < bestj)) { bestv = tot; bestj = j; }
        }
        __syncthreads();
    }
    if (t == 0) g_idx[row] = bestj;
}

// ---------------------------------------------------------------------------
// 3) gather: out[b,i,:] = Y[b, g_idx[b,i], :]
// ---------------------------------------------------------------------------
__global__ void __launch_bounds__(256) gather_kernel(const float* __restrict__ Y,
                                                     float* __restrict__ out) {
    int row  = blockIdx.x >> 2;
    int part = blockIdx.x & 3;
    int bb   = row >> 8;
    int src  = g_idx[row];
    const float4* yp = (const float4*)(Y + (size_t)(bb * CDIM + src) * HW);
    float4*       op = (float4*)(out + (size_t)row * HW);
    int e = part * 256 + threadIdx.x;
    op[e] = yp[e];
}

// ---------------------------------------------------------------------------
extern "C" void kernel_launch(void* const* d_in, const int* in_sizes, int n_in,
                              void* d_out, int out_size) {
    const float* x = (const float*)d_in[0];
    const float* y = (const float*)d_in[1];
    float* out = (float*)d_out;

    dim3 g(CDIM / 64, CDIM / 64, BATCH * KSPLIT);   // 4 x 4 x 64 = 1024 CTAs
    gemm_bf16_kernel<<<g, 256>>>(x, y);

    rescore_kernel<<<BATCH * CDIM, 256>>>(x, y);

    gather_kernel<<<BATCH * CDIM * 4, 256>>>(y, out);
}

// round 7
// speedup vs baseline: 3.4563x; 1.1975x over previous
#include <cuda_runtime.h>
#include <cuda_bf16.h>
#include <stdint.h>

#define BATCH 16
#define CDIM 256
#define HW 4096
#define KC 32                 // k-chunk (bf16 elems per row per stage)
#define KSPLIT 8
#define KSEG (HW / KSPLIT)    // 512
#define NKCS (KSEG / KC)      // 16 chunks per CTA
#define SSTR 40               // smem row stride in bf16 (80B; conflict-free ldsm)
#define TAU 8.0f

__device__ float g_part[KSPLIT][BATCH * CDIM * CDIM];   // 32 MB partial dist
__device__ int   g_idx[BATCH * CDIM];

// ---------------- helpers ----------------
__device__ __forceinline__ uint32_t bf2(float x, float y) {
    __nv_bfloat162 h = __floats2bfloat162_rn(x, y);
    return *reinterpret_cast<uint32_t*>(&h);
}
__device__ __forceinline__ uint32_t smaddr(const void* p) {
    return (uint32_t)__cvta_generic_to_shared(p);
}
__device__ __forceinline__ void ldsm4(uint32_t a, uint32_t* r) {
    asm volatile("ldmatrix.sync.aligned.m8n8.x4.shared.b16 {%0,%1,%2,%3}, [%4];"
                 : "=r"(r[0]), "=r"(r[1]), "=r"(r[2]), "=r"(r[3]) : "r"(a));
}
__device__ __forceinline__ void mma_bf16(float* d, const uint32_t* a, const uint32_t* b) {
    asm volatile("mma.sync.aligned.m16n8k16.row.col.f32.bf16.bf16.f32 "
                 "{%0,%1,%2,%3}, {%4,%5,%6,%7}, {%8,%9}, {%0,%1,%2,%3};"
                 : "+f"(d[0]), "+f"(d[1]), "+f"(d[2]), "+f"(d[3])
                 : "r"(a[0]), "r"(a[1]), "r"(a[2]), "r"(a[3]), "r"(b[0]), "r"(b[1]));
}

// ---------------------------------------------------------------------------
// 1) partial dist^2 over one k-segment: |y|^2_seg - 2*dot_seg (bf16 hi MMA).
//    CTA: 128(i) x 128(j) x kseg, 512 threads, 16 warps 4(i)x4(j), wtile 32x32.
//    Loader: 8 lanes/row x 16B = full 128B line per LDG instruction.
// ---------------------------------------------------------------------------
__global__ void __launch_bounds__(512) gemm_bf16_kernel(const float* __restrict__ X,
                                                        const float* __restrict__ Y) {
    __shared__ __nv_bfloat16 sA[2][128 * SSTR];
    __shared__ __nv_bfloat16 sB[2][128 * SSTR];
    __shared__ float ynS[128];

    const int b  = blockIdx.z >> 3;
    const int ks = blockIdx.z & 7;
    const int i0 = blockIdx.y * 128;
    const int j0 = blockIdx.x * 128;
    const int t  = threadIdx.x;

    // loader: o = lane-in-row (8 x float4 = 128B per row), rg = row group
    const int o  = t & 7;
    const int rg = t >> 3;           // 0..63
    // q=0,1 -> A rows rg, rg+64 ; q=2,3 -> B rows rg, rg+64
    const float* srcq[4];
    int smoff[4];
#pragma unroll
    for (int q = 0; q < 4; ++q) {
        const int row = rg + 64 * (q & 1);
        const float* base = (q < 2) ? (X + (size_t)(b * CDIM + i0 + row) * HW)
                                    : (Y + (size_t)(b * CDIM + j0 + row) * HW);
        srcq[q] = base + ks * KSEG + o * 4;
        smoff[q] = row * SSTR + o * 4;
    }

    float ysq0 = 0.f, ysq1 = 0.f;
    float4 v[4];

    // prologue: chunk 0
#pragma unroll
    for (int q = 0; q < 4; ++q) v[q] = *(const float4*)(srcq[q]);
    ysq0 += v[2].x * v[2].x + v[2].y * v[2].y + v[2].z * v[2].z + v[2].w * v[2].w;
    ysq1 += v[3].x * v[3].x + v[3].y * v[3].y + v[3].z * v[3].z + v[3].w * v[3].w;
#pragma unroll
    for (int q = 0; q < 4; ++q) {
        uint2 pk = make_uint2(bf2(v[q].x, v[q].y), bf2(v[q].z, v[q].w));
        *(uint2*)((q < 2 ? sA[0] : sB[0]) + smoff[q]) = pk;
    }
    __syncthreads();

    // warp tiling: 16 warps = 4(i) x 4(j), warp tile 32(m) x 32(n)
    const int lane = t & 31;
    const int w    = t >> 5;
    const int i0w  = (w >> 2) * 32;
    const int j0w  = (w & 3) * 32;
    const int arow = i0w + (lane & 15);
    const int acol = (lane >> 4) * 8;
    const int bn   = j0w + (lane & 7) + ((lane >> 4) << 3);
    const int bk   = ((lane >> 3) & 1) * 8;

    float acc[2][4][4];
#pragma unroll
    for (int m = 0; m < 2; ++m)
#pragma unroll
        for (int n = 0; n < 4; ++n)
#pragma unroll
            for (int e = 0; e < 4; ++e) acc[m][n][e] = 0.f;

    int p = 0;
    for (int kc = 0; kc < NKCS; ++kc) {
        const bool more = (kc + 1 < NKCS);
        if (more) {
#pragma unroll
            for (int q = 0; q < 4; ++q) v[q] = *(const float4*)(srcq[q] + (kc + 1) * KC);
            ysq0 += v[2].x * v[2].x + v[2].y * v[2].y + v[2].z * v[2].z + v[2].w * v[2].w;
            ysq1 += v[3].x * v[3].x + v[3].y * v[3].y + v[3].z * v[3].z + v[3].w * v[3].w;
        }

#pragma unroll
        for (int s = 0; s < 2; ++s) {   // two k16 steps per chunk
            uint32_t ah0[4], ah1[4], bh0[4], bh1[4];
            const int ao = arow * SSTR + s * 16 + acol;
            ldsm4(smaddr(sA[p] + ao), ah0);
            ldsm4(smaddr(sA[p] + ao + 16 * SSTR), ah1);
            const int bo = bn * SSTR + s * 16 + bk;
            ldsm4(smaddr(sB[p] + bo), bh0);
            ldsm4(smaddr(sB[p] + bo + 16 * SSTR), bh1);
            mma_bf16(acc[0][0], ah0, bh0);
            mma_bf16(acc[0][1], ah0, bh0 + 2);
            mma_bf16(acc[0][2], ah0, bh1);
            mma_bf16(acc[0][3], ah0, bh1 + 2);
            mma_bf16(acc[1][0], ah1, bh0);
            mma_bf16(acc[1][1], ah1, bh0 + 2);
            mma_bf16(acc[1][2], ah1, bh1);
            mma_bf16(acc[1][3], ah1, bh1 + 2);
        }

        if (more) {
            const int np = p ^ 1;
#pragma unroll
            for (int q = 0; q < 4; ++q) {
                uint2 pk = make_uint2(bf2(v[q].x, v[q].y), bf2(v[q].z, v[q].w));
                *(uint2*)((q < 2 ? sA[np] : sB[np]) + smoff[q]) = pk;
            }
        }
        __syncthreads();
        p ^= 1;
    }

    // partial ynorm: reduce over the 8 lanes sharing a row (o = 0..7)
#pragma unroll
    for (int off = 4; off; off >>= 1) {
        ysq0 += __shfl_xor_sync(0xffffffffu, ysq0, off);
        ysq1 += __shfl_xor_sync(0xffffffffu, ysq1, off);
    }
    if (o == 0) { ynS[rg] = ysq0; ynS[rg + 64] = ysq1; }
    __syncthreads();

    float* gout = g_part[ks];
#pragma unroll
    for (int mi = 0; mi < 2; ++mi) {
#pragma unroll
        for (int nb = 0; nb < 4; ++nb) {
            const int jc = j0w + nb * 8 + (lane & 3) * 2;
            float2 yn = *(float2*)&ynS[jc];
            const int grow = b * CDIM + i0 + i0w + mi * 16 + (lane >> 2);
            float2 d0, d1;
            d0.x = yn.x - 2.f * acc[mi][nb][0];
            d0.y = yn.y - 2.f * acc[mi][nb][1];
            d1.x = yn.x - 2.f * acc[mi][nb][2];
            d1.y = yn.y - 2.f * acc[mi][nb][3];
            *(float2*)&gout[(size_t)grow * CDIM + j0 + jc] = d0;
            *(float2*)&gout[(size_t)(grow + 8) * CDIM + j0 + jc] = d1;
        }
    }
}

// ---------------------------------------------------------------------------
// 2) argmin (sum of 8 partials) with exact-fp32 rescue. One block per row.
// ---------------------------------------------------------------------------
__global__ void __launch_bounds__(256) rescore_kernel(const float* __restrict__ X,
                                                      const float* __restrict__ Y) {
    const int row = blockIdx.x;           // b*CDIM + i
    const int b   = row >> 8;
    const int t   = threadIdx.x;

    __shared__ float s_red[8];
    __shared__ float s_minv;
    __shared__ int   s_cnt;
    __shared__ int   s_lst[256];

    const size_t off = (size_t)row * CDIM + t;
    float d = 0.f;
#pragma unroll
    for (int k = 0; k < KSPLIT; ++k) d += g_part[k][off];

    float vv = d;
#pragma unroll
    for (int o = 16; o; o >>= 1) vv = fminf(vv, __shfl_down_sync(0xffffffffu, vv, o));
    if ((t & 31) == 0) s_red[t >> 5] = vv;
    __syncthreads();
    if (t == 0) {
        float m = s_red[0];
#pragma unroll
        for (int i = 1; i < 8; ++i) m = fminf(m, s_red[i]);
        s_minv = m;
        s_cnt = 0;
    }
    __syncthreads();

    if (d <= s_minv + TAU) {
        int pos = atomicAdd(&s_cnt, 1);
        s_lst[pos] = t;
    }
    __syncthreads();

    const int n = s_cnt;
    if (n == 1) {
        if (t == 0) g_idx[row] = s_lst[0];
        return;
    }

    const float* xr = X + (size_t)row * HW;
    float bestv = 3.4e38f;
    int   bestj = 0x7fffffff;
    for (int c = 0; c < n; ++c) {
        const int j = s_lst[c];
        const float* yr = Y + (size_t)(b * CDIM + j) * HW;
        float s = 0.f;
#pragma unroll
        for (int q = 0; q < 4; ++q) {
            float4 xv = ((const float4*)xr)[t + q * 256];
            float4 yv = ((const float4*)yr)[t + q * 256];
            float dx = xv.x - yv.x, dy = xv.y - yv.y, dz = xv.z - yv.z, dw = xv.w - yv.w;
            s += dx * dx + dy * dy + dz * dz + dw * dw;
        }
#pragma unroll
        for (int o = 16; o; o >>= 1) s += __shfl_down_sync(0xffffffffu, s, o);
        if ((t & 31) == 0) s_red[t >> 5] = s;
        __syncthreads();
        if (t == 0) {
            float tot = 0.f;
#pragma unroll
            for (int i = 0; i < 8; ++i) tot += s_red[i];
            if (tot < bestv || (tot == bestv && j < bestj)) { bestv = tot; bestj = j; }
        }
        __syncthreads();
    }
    if (t == 0) g_idx[row] = bestj;
}

// ---------------------------------------------------------------------------
// 3) gather: out[b,i,:] = Y[b, g_idx[b,i], :]
// ---------------------------------------------------------------------------
__global__ void __launch_bounds__(256) gather_kernel(const float* __restrict__ Y,
                                                     float* __restrict__ out) {
    int row  = blockIdx.x >> 2;
    int part = blockIdx.x & 3;
    int bb   = row >> 8;
    int src  = g_idx[row];
    const float4* yp = (const float4*)(Y + (size_t)(bb * CDIM + src) * HW);
    float4*       op = (float4*)(out + (size_t)row * HW);
    int e = part * 256 + threadIdx.x;
    op[e] = yp[e];
}

// ---------------------------------------------------------------------------
extern "C" void kernel_launch(void* const* d_in, const int* in_sizes, int n_in,
                              void* d_out, int out_size) {
    const float* x = (const float*)d_in[0];
    const float* y = (const float*)d_in[1];
    float* out = (float*)d_out;

    dim3 g(CDIM / 128, CDIM / 128, BATCH * KSPLIT);   // 2 x 2 x 128 = 512 CTAs
    gemm_bf16_kernel<<<g, 512>>>(x, y);

    rescore_kernel<<<BATCH * CDIM, 256>>>(x, y);

    gather_kernel<<<BATCH * CDIM * 4, 256>>>(y, out);
}